// round 13
// baseline (speedup 1.0000x reference)
#include <cuda_runtime.h>
#include <cuda_fp16.h>

// Problem: B=2, C=4, D=64, H=256, W=256
#define HW    65536        // H*W
#define DHW   4194304      // D*H*W
#define DHW4  1048576      // DHW/4
#define NQ    2097152      // threads, 4 voxels each
#define NELEM 25165824.0   // B*(C-1)*DHW

// Planar scratch: A = half2(p1,p2)/voxel, B = half(p3)/voxel, T = uint8/voxel
__device__ __align__(16) __half2       g_A[2 * DHW];
__device__ __align__(16) __half        g_B[2 * DHW];
__device__ __align__(16) unsigned char g_T[2 * DHW];
__device__ double   g_acc;
__device__ unsigned g_done = 0;

__device__ __forceinline__ unsigned h2u(__half2 h) { return *(unsigned*)&h; }
__device__ __forceinline__ __half2 u2h(unsigned u) { return *(__half2*)&u; }

// ---------------- Pass 1: softmax (4 voxels/thread) + target byte-encode -----
__global__ void __launch_bounds__(256)
softmax_kernel(const float* __restrict__ logits, const int* __restrict__ targets) {
    int t = blockIdx.x * blockDim.x + threadIdx.x;
    if (t == 0) g_acc = 0.0;
    if (t >= NQ) return;
    int b  = t >> 20;
    int v4 = t & (DHW4 - 1);
    const float4* L = (const float4*)logits + (size_t)b * 4 * DHW4 + v4;
    float4 x0 = L[0 * DHW4];
    float4 x1 = L[1 * DHW4];
    float4 x2 = L[2 * DHW4];
    float4 x3 = L[3 * DHW4];
    float4 p1, p2, p3;
#define SM1(comp) {                                                       \
        float a = x0.comp, bb = x1.comp, c = x2.comp, dd = x3.comp;       \
        float m  = fmaxf(fmaxf(a, bb), fmaxf(c, dd));                     \
        float e0 = __expf(a - m), e1 = __expf(bb - m);                    \
        float e2 = __expf(c - m), e3 = __expf(dd - m);                    \
        float inv = __frcp_rn(e0 + e1 + e2 + e3);                        \
        p1.comp = e1 * inv; p2.comp = e2 * inv; p3.comp = e3 * inv; }
    SM1(x) SM1(y) SM1(z) SM1(w)
#undef SM1
    size_t v = ((size_t)b * DHW) + ((size_t)v4 << 2);
    uint4 a4;
    a4.x = h2u(__floats2half2_rn(p1.x, p2.x));
    a4.y = h2u(__floats2half2_rn(p1.y, p2.y));
    a4.z = h2u(__floats2half2_rn(p1.z, p2.z));
    a4.w = h2u(__floats2half2_rn(p1.w, p2.w));
    *(uint4*)(g_A + v) = a4;
    uint2 b2;
    b2.x = h2u(__floats2half2_rn(p3.x, p3.y));
    b2.y = h2u(__floats2half2_rn(p3.z, p3.w));
    *(uint2*)(g_B + v) = b2;
    int4 tt = *((const int4*)targets + ((size_t)b * DHW4) + v4);
    unsigned tw = (unsigned)tt.x | ((unsigned)tt.y << 8)
                | ((unsigned)tt.z << 16) | ((unsigned)tt.w << 24);
    *(unsigned*)(g_T + v) = tw;
}

// ---------------- Pass 2: stencil + loss + reduction -------------------------
__global__ void __launch_bounds__(256, 6)
loss_kernel(float* __restrict__ out) {
    int t  = blockIdx.x * blockDim.x + threadIdx.x;
    int w4 = t & 63;
    int h  = (t >> 6) & 255;
    int d  = (t >> 14) & 63;
    int b  = t >> 20;
    size_t v = (size_t)d * HW + h * 256 + (w4 << 2);

    const __half2*       A  = g_A + (size_t)b * DHW;
    const __half*        Bp = g_B + (size_t)b * DHW;
    const unsigned char* Tb = g_T + (size_t)b * DHW;

    const bool d0ok = (d > 0), d1ok = (d < 63);
    const bool h0ok = (h > 0), h1ok = (h < 255);
    const bool w0ok = (w4 > 0), w1ok = (w4 < 63);
    const uint4 z4 = make_uint4(0, 0, 0, 0);
    const uint2 z2 = make_uint2(0, 0);

    // ---- loads (front-batched) ----
    uint4 Ac  = *(const uint4*)(A + v);
    uint4 Adm = d0ok ? *(const uint4*)(A + v - HW)  : z4;
    uint4 Adp = d1ok ? *(const uint4*)(A + v + HW)  : z4;
    uint4 Ahm = h0ok ? *(const uint4*)(A + v - 256) : z4;
    uint4 Ahp = h1ok ? *(const uint4*)(A + v + 256) : z4;
    unsigned lfA = w0ok ? *(const unsigned*)(A + v - 1) : 0u;
    unsigned rtA = w1ok ? *(const unsigned*)(A + v + 4) : 0u;

    uint2 Bc  = *(const uint2*)(Bp + v);
    uint2 Bdm = d0ok ? *(const uint2*)(Bp + v - HW)  : z2;
    uint2 Bdp = d1ok ? *(const uint2*)(Bp + v + HW)  : z2;
    uint2 Bhm = h0ok ? *(const uint2*)(Bp + v - 256) : z2;
    uint2 Bhp = h1ok ? *(const uint2*)(Bp + v + 256) : z2;
    unsigned bL = w0ok ? *(const unsigned*)(Bp + v - 2) : 0u;
    unsigned bR = w1ok ? *(const unsigned*)(Bp + v + 4) : 0u;

    unsigned tc4 = *(const unsigned*)(Tb + v);
    unsigned tdm = d0ok ? *(const unsigned*)(Tb + v - HW)  : 0u;
    unsigned tdp = d1ok ? *(const unsigned*)(Tb + v + HW)  : 0u;
    unsigned thm = h0ok ? *(const unsigned*)(Tb + v - 256) : 0u;
    unsigned thp = h1ok ? *(const unsigned*)(Tb + v + 256) : 0u;
    unsigned twL = w0ok ? *(const unsigned*)(Tb + v - 4)   : 0u;
    unsigned twR = w1ok ? *(const unsigned*)(Tb + v + 4)   : 0u;

    // ---- A stencil: per voxel j, half2 = classes (1,2) ----
    const __half2 m6 = __floats2half2_rn(-6.f, -6.f);
    const __half2* cA = (const __half2*)&Ac;
    __half2 sA[4];
    {
        const __half2* dm = (const __half2*)&Adm;
        const __half2* dp = (const __half2*)&Adp;
        const __half2* hm = (const __half2*)&Ahm;
        const __half2* hp = (const __half2*)&Ahp;
#pragma unroll
        for (int j = 0; j < 4; ++j) {
            __half2 lf = (j == 0) ? u2h(lfA) : cA[j - 1];
            __half2 rt = (j == 3) ? u2h(rtA) : cA[j + 1];
            __half2 s = __hadd2(__hadd2(dm[j], dp[j]), __hadd2(hm[j], hp[j]));
            s = __hadd2(s, __hadd2(lf, rt));
            sA[j] = __hfma2(cA[j], m6, s);
        }
    }

    // ---- B stencil: pairs (v0,v1) and (v2,v3), class 3 ----
    unsigned L0  = __byte_perm(Bc.x, bL, 0x1076);   // (B[v-1], v0)
    unsigned mid = __byte_perm(Bc.x, Bc.y, 0x5432); // (v1, v2)
    unsigned R1  = __byte_perm(Bc.y, bR, 0x5432);   // (v3, B[v+4])
    __half2 sB0 = __hadd2(__hadd2(u2h(Bdm.x), u2h(Bdp.x)),
                          __hadd2(u2h(Bhm.x), u2h(Bhp.x)));
    sB0 = __hadd2(sB0, __hadd2(u2h(L0), u2h(mid)));
    sB0 = __hfma2(u2h(Bc.x), m6, sB0);
    __half2 sB1 = __hadd2(__hadd2(u2h(Bdm.y), u2h(Bdp.y)),
                          __hadd2(u2h(Bhm.y), u2h(Bhp.y)));
    sB1 = __hadd2(sB1, __hadd2(u2h(mid), u2h(R1)));
    sB1 = __hfma2(u2h(Bc.y), m6, sB1);

    // ---- byte-SIMD target |Laplacian| per class (bytes 0..6) ----
    unsigned lt4 = __byte_perm(tc4, twL, 0x2107);
    unsigned rt4 = __byte_perm(tc4, twR, 0x4321);
    const unsigned ONE = 0x01010101u;
    unsigned absT[3];
#pragma unroll
    for (int c = 0; c < 3; ++c) {
        unsigned cc = ONE * (unsigned)(c + 1);
        unsigned cnt = __vsub4(0u, __vcmpeq4(tdm, cc));
        cnt = __vsub4(cnt, __vcmpeq4(tdp, cc));
        cnt = __vsub4(cnt, __vcmpeq4(thm, cc));
        cnt = __vsub4(cnt, __vcmpeq4(thp, cc));
        cnt = __vsub4(cnt, __vcmpeq4(lt4, cc));
        cnt = __vsub4(cnt, __vcmpeq4(rt4, cc));
        unsigned e = __vcmpeq4(tc4, cc);           // 0xFF where center == class
        absT[c] = (cnt & ~e) | (__vsub4(0x06060606u, cnt) & e);
    }

    // ---- loss accumulation (I2F path) ----
    float acc = 0.f;
#pragma unroll
    for (int j = 0; j < 4; ++j) {
        float2 f12 = __half22float2(__habs2(sA[j]));
        __half2 sb = (j < 2) ? sB0 : sB1;
        float f3 = fabsf((j & 1) ? __half2float(__high2half(sb))
                                 : __half2float(__low2half(sb)));
        float t1 = (float)((absT[0] >> (j * 8)) & 0xFFu);
        float t2 = (float)((absT[1] >> (j * 8)) & 0xFFu);
        float t3 = (float)((absT[2] >> (j * 8)) & 0xFFu);
        float d1 = f12.x - t1, d2 = f12.y - t2, d3 = f3 - t3;
        acc = fmaf(d1, d1, acc);
        acc = fmaf(d2, d2, acc);
        acc = fmaf(d3, d3, acc);
    }

    // ---- block reduction -> double atomic -> last-block finalize ----
#pragma unroll
    for (int o = 16; o; o >>= 1) acc += __shfl_down_sync(0xffffffffu, acc, o);
    __shared__ float ws[8];
    __shared__ unsigned ticket;
    int lane = threadIdx.x & 31, wid = threadIdx.x >> 5;
    if (lane == 0) ws[wid] = acc;
    __syncthreads();
    if (wid == 0) {
        acc = (lane < 8) ? ws[lane] : 0.f;
#pragma unroll
        for (int o = 4; o; o >>= 1) acc += __shfl_down_sync(0xffffffffu, acc, o);
        if (lane == 0) {
            atomicAdd(&g_acc, (double)acc);
            __threadfence();
            ticket = atomicAdd(&g_done, 1u);
        }
    }
    __syncthreads();
    if (threadIdx.x == 0 && ticket == gridDim.x - 1) {
        double total = atomicAdd(&g_acc, 0.0);
        out[0] = (float)(total * (1.0 / NELEM));
        g_done = 0;
    }
}

extern "C" void kernel_launch(void* const* d_in, const int* in_sizes, int n_in,
                              void* d_out, int out_size) {
    const float* logits  = (const float*)d_in[0];
    const int*   targets = (const int*)d_in[1];
    float* out = (float*)d_out;

    softmax_kernel<<<NQ / 256, 256>>>(logits, targets);
    loss_kernel<<<NQ / 256, 256>>>(out);
}

// round 14
// speedup vs baseline: 1.1099x; 1.1099x over previous
#include <cuda_runtime.h>
#include <cuda_fp16.h>

// Problem: B=2, C=4, D=64, H=256, W=256
#define HW    65536        // H*W
#define DHW   4194304      // D*H*W
#define DHW4  1048576      // DHW/4
#define NQ    2097152      // threads, 4 voxels each
#define NELEM 25165824.0   // B*(C-1)*DHW

// Planar scratch: A = half2(p1,p2)/voxel, B = half(p3)/voxel, T = uint8/voxel
__device__ __align__(16) __half2       g_A[2 * DHW];
__device__ __align__(16) __half        g_B[2 * DHW];
__device__ __align__(16) unsigned char g_T[2 * DHW];
__device__ double   g_acc;
__device__ unsigned g_done = 0;

__device__ __forceinline__ unsigned h2u(__half2 h) { return *(unsigned*)&h; }
__device__ __forceinline__ __half2 u2h(unsigned u) { return *(__half2*)&u; }

// ---------------- Pass 1: softmax + target byte-encode ----------------------
__global__ void __launch_bounds__(256)
softmax_kernel(const float* __restrict__ logits, const int* __restrict__ targets) {
    int t = blockIdx.x * blockDim.x + threadIdx.x;
    if (t == 0) g_acc = 0.0;
    if (t >= NQ) return;
    int b  = t >> 20;
    int v4 = t & (DHW4 - 1);
    const float4* L = (const float4*)logits + (size_t)b * 4 * DHW4 + v4;
    float4 x0 = L[0 * DHW4];
    float4 x1 = L[1 * DHW4];
    float4 x2 = L[2 * DHW4];
    float4 x3 = L[3 * DHW4];
    float4 p1, p2, p3;
#define SM1(comp) {                                                       \
        float a = x0.comp, bb = x1.comp, c = x2.comp, dd = x3.comp;       \
        float m  = fmaxf(fmaxf(a, bb), fmaxf(c, dd));                     \
        float e0 = __expf(a - m), e1 = __expf(bb - m);                    \
        float e2 = __expf(c - m), e3 = __expf(dd - m);                    \
        float inv = __frcp_rn(e0 + e1 + e2 + e3);                        \
        p1.comp = e1 * inv; p2.comp = e2 * inv; p3.comp = e3 * inv; }
    SM1(x) SM1(y) SM1(z) SM1(w)
#undef SM1
    size_t v = ((size_t)b * DHW) + ((size_t)v4 << 2);
    uint4 a4;
    a4.x = h2u(__floats2half2_rn(p1.x, p2.x));
    a4.y = h2u(__floats2half2_rn(p1.y, p2.y));
    a4.z = h2u(__floats2half2_rn(p1.z, p2.z));
    a4.w = h2u(__floats2half2_rn(p1.w, p2.w));
    *(uint4*)(g_A + v) = a4;
    uint2 b2;
    b2.x = h2u(__floats2half2_rn(p3.x, p3.y));
    b2.y = h2u(__floats2half2_rn(p3.z, p3.w));
    *(uint2*)(g_B + v) = b2;
    int4 tt = *((const int4*)targets + ((size_t)b * DHW4) + v4);
    unsigned tw = (unsigned)tt.x | ((unsigned)tt.y << 8)
                | ((unsigned)tt.z << 16) | ((unsigned)tt.w << 24);
    *(unsigned*)(g_T + v) = tw;
}

// ---------------- Pass 2: stencil + loss + reduction -------------------------
__global__ void __launch_bounds__(256, 5)
loss_kernel(float* __restrict__ out) {
    int t  = blockIdx.x * blockDim.x + threadIdx.x;
    int w4 = t & 63;
    int h  = (t >> 6) & 255;
    int d  = (t >> 14) & 63;
    int b  = t >> 20;
    size_t v = (size_t)d * HW + h * 256 + (w4 << 2);

    const __half2*       A  = g_A + (size_t)b * DHW;
    const __half*        Bp = g_B + (size_t)b * DHW;
    const unsigned char* Tb = g_T + (size_t)b * DHW;

    const bool d0ok = (d > 0), d1ok = (d < 63);
    const bool h0ok = (h > 0), h1ok = (h < 255);
    const bool w0ok = (w4 > 0), w1ok = (w4 < 63);
    const uint4 z4 = make_uint4(0, 0, 0, 0);
    const uint2 z2 = make_uint2(0, 0);

    // ---- loads (front-batched) ----
    uint4 Ac  = *(const uint4*)(A + v);
    uint4 Adm = d0ok ? *(const uint4*)(A + v - HW)  : z4;
    uint4 Adp = d1ok ? *(const uint4*)(A + v + HW)  : z4;
    uint4 Ahm = h0ok ? *(const uint4*)(A + v - 256) : z4;
    uint4 Ahp = h1ok ? *(const uint4*)(A + v + 256) : z4;
    unsigned lfA = w0ok ? *(const unsigned*)(A + v - 1) : 0u;
    unsigned rtA = w1ok ? *(const unsigned*)(A + v + 4) : 0u;

    uint2 Bc  = *(const uint2*)(Bp + v);
    uint2 Bdm = d0ok ? *(const uint2*)(Bp + v - HW)  : z2;
    uint2 Bdp = d1ok ? *(const uint2*)(Bp + v + HW)  : z2;
    uint2 Bhm = h0ok ? *(const uint2*)(Bp + v - 256) : z2;
    uint2 Bhp = h1ok ? *(const uint2*)(Bp + v + 256) : z2;
    unsigned bL = w0ok ? *(const unsigned*)(Bp + v - 2) : 0u;
    unsigned bR = w1ok ? *(const unsigned*)(Bp + v + 4) : 0u;

    unsigned tc4 = *(const unsigned*)(Tb + v);
    unsigned tdm = d0ok ? *(const unsigned*)(Tb + v - HW)  : 0u;
    unsigned tdp = d1ok ? *(const unsigned*)(Tb + v + HW)  : 0u;
    unsigned thm = h0ok ? *(const unsigned*)(Tb + v - 256) : 0u;
    unsigned thp = h1ok ? *(const unsigned*)(Tb + v + 256) : 0u;
    unsigned twL = w0ok ? *(const unsigned*)(Tb + v - 4)   : 0u;
    unsigned twR = w1ok ? *(const unsigned*)(Tb + v + 4)   : 0u;

    // ---- A stencil: per voxel j, half2 = classes (1,2) ----
    const __half2 m6 = __floats2half2_rn(-6.f, -6.f);
    const __half2* cA = (const __half2*)&Ac;
    __half2 sA[4];
    {
        const __half2* dm = (const __half2*)&Adm;
        const __half2* dp = (const __half2*)&Adp;
        const __half2* hm = (const __half2*)&Ahm;
        const __half2* hp = (const __half2*)&Ahp;
#pragma unroll
        for (int j = 0; j < 4; ++j) {
            __half2 lf = (j == 0) ? u2h(lfA) : cA[j - 1];
            __half2 rt = (j == 3) ? u2h(rtA) : cA[j + 1];
            __half2 s = __hadd2(__hadd2(dm[j], dp[j]), __hadd2(hm[j], hp[j]));
            s = __hadd2(s, __hadd2(lf, rt));
            sA[j] = __hfma2(cA[j], m6, s);
        }
    }

    // ---- B stencil: pairs (v0,v1) and (v2,v3), class 3 ----
    unsigned L0  = __byte_perm(Bc.x, bL, 0x1076);   // (B[v-1], v0)
    unsigned mid = __byte_perm(Bc.x, Bc.y, 0x5432); // (v1, v2)
    unsigned R1  = __byte_perm(Bc.y, bR, 0x5432);   // (v3, B[v+4])
    __half2 sB0 = __hadd2(__hadd2(u2h(Bdm.x), u2h(Bdp.x)),
                          __hadd2(u2h(Bhm.x), u2h(Bhp.x)));
    sB0 = __hadd2(sB0, __hadd2(u2h(L0), u2h(mid)));
    sB0 = __hfma2(u2h(Bc.x), m6, sB0);
    __half2 sB1 = __hadd2(__hadd2(u2h(Bdm.y), u2h(Bdp.y)),
                          __hadd2(u2h(Bhm.y), u2h(Bhp.y)));
    sB1 = __hadd2(sB1, __hadd2(u2h(mid), u2h(R1)));
    sB1 = __hfma2(u2h(Bc.y), m6, sB1);

    // ---- byte-SIMD target |Laplacian| per class (bytes 0..6) ----
    unsigned lt4 = __byte_perm(tc4, twL, 0x2107);
    unsigned rt4 = __byte_perm(tc4, twR, 0x4321);
    const unsigned ONE = 0x01010101u;
    unsigned absT[3];
#pragma unroll
    for (int c = 0; c < 3; ++c) {
        unsigned cc = ONE * (unsigned)(c + 1);
        unsigned cnt = __vsub4(0u, __vcmpeq4(tdm, cc));
        cnt = __vsub4(cnt, __vcmpeq4(tdp, cc));
        cnt = __vsub4(cnt, __vcmpeq4(thm, cc));
        cnt = __vsub4(cnt, __vcmpeq4(thp, cc));
        cnt = __vsub4(cnt, __vcmpeq4(lt4, cc));
        cnt = __vsub4(cnt, __vcmpeq4(rt4, cc));
        unsigned e = __vcmpeq4(tc4, cc);           // 0xFF where center == class
        absT[c] = (cnt & ~e) | (__vsub4(0x06060606u, cnt) & e);
    }

    // ---- loss accumulation (I2F path) ----
    float acc = 0.f;
#pragma unroll
    for (int j = 0; j < 4; ++j) {
        float2 f12 = __half22float2(__habs2(sA[j]));
        __half2 sb = (j < 2) ? sB0 : sB1;
        float f3 = fabsf((j & 1) ? __half2float(__high2half(sb))
                                 : __half2float(__low2half(sb)));
        float t1 = (float)((absT[0] >> (j * 8)) & 0xFFu);
        float t2 = (float)((absT[1] >> (j * 8)) & 0xFFu);
        float t3 = (float)((absT[2] >> (j * 8)) & 0xFFu);
        float d1 = f12.x - t1, d2 = f12.y - t2, d3 = f3 - t3;
        acc = fmaf(d1, d1, acc);
        acc = fmaf(d2, d2, acc);
        acc = fmaf(d3, d3, acc);
    }

    // ---- block reduction -> double atomic -> last-block finalize ----
#pragma unroll
    for (int o = 16; o; o >>= 1) acc += __shfl_down_sync(0xffffffffu, acc, o);
    __shared__ float ws[8];
    __shared__ unsigned ticket;
    int lane = threadIdx.x & 31, wid = threadIdx.x >> 5;
    if (lane == 0) ws[wid] = acc;
    __syncthreads();
    if (wid == 0) {
        acc = (lane < 8) ? ws[lane] : 0.f;
#pragma unroll
        for (int o = 4; o; o >>= 1) acc += __shfl_down_sync(0xffffffffu, acc, o);
        if (lane == 0) {
            atomicAdd(&g_acc, (double)acc);
            __threadfence();
            ticket = atomicAdd(&g_done, 1u);
        }
    }
    __syncthreads();
    if (threadIdx.x == 0 && ticket == gridDim.x - 1) {
        double total = atomicAdd(&g_acc, 0.0);
        out[0] = (float)(total * (1.0 / NELEM));
        g_done = 0;
    }
}

extern "C" void kernel_launch(void* const* d_in, const int* in_sizes, int n_in,
                              void* d_out, int out_size) {
    const float* logits  = (const float*)d_in[0];
    const int*   targets = (const int*)d_in[1];
    float* out = (float*)d_out;

    softmax_kernel<<<NQ / 256, 256>>>(logits, targets);
    loss_kernel<<<NQ / 256, 256>>>(out);
}

// round 15
// speedup vs baseline: 1.1558x; 1.0414x over previous
#include <cuda_runtime.h>
#include <cuda_fp16.h>

// Problem: B=2, C=4, D=64, H=256, W=256
#define HW    65536        // H*W
#define DHW   4194304      // D*H*W
#define DHW4  1048576      // DHW/4
#define NQ    2097152      // threads, 4 voxels each
#define NELEM 25165824.0   // B*(C-1)*DHW

// Planar scratch: A = half2(p1,p2)/voxel (33.5MB), B = half(p3)/voxel (16.8MB),
// T = uint8 target/voxel (8.4MB)
__device__ __align__(16) __half2       g_A[2 * DHW];
__device__ __align__(16) __half        g_B[2 * DHW];
__device__ __align__(16) unsigned char g_T[2 * DHW];
__device__ double   g_acc;
__device__ unsigned g_done = 0;

__device__ __forceinline__ unsigned h2u(__half2 h) { return *(unsigned*)&h; }
__device__ __forceinline__ __half2 u2h(unsigned u) { return *(__half2*)&u; }

// ---------------- Pass 1: softmax + target byte-encode ----------------------
__global__ void __launch_bounds__(256)
softmax_kernel(const float* __restrict__ logits, const int* __restrict__ targets) {
    int t = blockIdx.x * blockDim.x + threadIdx.x;
    if (t == 0) g_acc = 0.0;
    if (t >= NQ) return;
    int b  = t >> 20;
    int v4 = t & (DHW4 - 1);
    const float4* L = (const float4*)logits + (size_t)b * 4 * DHW4 + v4;
    float4 x0 = L[0 * DHW4];
    float4 x1 = L[1 * DHW4];
    float4 x2 = L[2 * DHW4];
    float4 x3 = L[3 * DHW4];
    float4 p1, p2, p3;
#define SM1(comp) {                                                       \
        float a = x0.comp, bb = x1.comp, c = x2.comp, dd = x3.comp;       \
        float m  = fmaxf(fmaxf(a, bb), fmaxf(c, dd));                     \
        float e0 = __expf(a - m), e1 = __expf(bb - m);                    \
        float e2 = __expf(c - m), e3 = __expf(dd - m);                    \
        float inv = __frcp_rn(e0 + e1 + e2 + e3);                        \
        p1.comp = e1 * inv; p2.comp = e2 * inv; p3.comp = e3 * inv; }
    SM1(x) SM1(y) SM1(z) SM1(w)
#undef SM1
    size_t v = ((size_t)b * DHW) + ((size_t)v4 << 2);
    uint4 a4;
    a4.x = h2u(__floats2half2_rn(p1.x, p2.x));
    a4.y = h2u(__floats2half2_rn(p1.y, p2.y));
    a4.z = h2u(__floats2half2_rn(p1.z, p2.z));
    a4.w = h2u(__floats2half2_rn(p1.w, p2.w));
    *(uint4*)(g_A + v) = a4;
    uint2 b2;
    b2.x = h2u(__floats2half2_rn(p3.x, p3.y));
    b2.y = h2u(__floats2half2_rn(p3.z, p3.w));
    *(uint2*)(g_B + v) = b2;
    int4 tt = *((const int4*)targets + ((size_t)b * DHW4) + v4);
    unsigned tw = (unsigned)tt.x | ((unsigned)tt.y << 8)
                | ((unsigned)tt.z << 16) | ((unsigned)tt.w << 24);
    *(unsigned*)(g_T + v) = tw;
}

// ---------------- Pass 2: stencil + loss + reduction -------------------------
__global__ void __launch_bounds__(256, 5)
loss_kernel(float* __restrict__ out) {
    int t  = blockIdx.x * blockDim.x + threadIdx.x;
    int w4 = t & 63;
    int h  = (t >> 6) & 255;
    int d  = (t >> 14) & 63;
    int b  = t >> 20;
    size_t v = (size_t)d * HW + h * 256 + (w4 << 2);

    const __half2*       A  = g_A + (size_t)b * DHW;
    const __half*        Bp = g_B + (size_t)b * DHW;
    const unsigned char* Tb = g_T + (size_t)b * DHW;

    const bool d0ok = (d > 0), d1ok = (d < 63);
    const bool h0ok = (h > 0), h1ok = (h < 255);
    const bool w0ok = (w4 > 0), w1ok = (w4 < 63);
    const uint4 z4 = make_uint4(0, 0, 0, 0);
    const uint2 z2 = make_uint2(0, 0);

    // ---- loads (front-batched) ----
    uint4 Ac  = *(const uint4*)(A + v);
    uint4 Adm = d0ok ? *(const uint4*)(A + v - HW)  : z4;
    uint4 Adp = d1ok ? *(const uint4*)(A + v + HW)  : z4;
    uint4 Ahm = h0ok ? *(const uint4*)(A + v - 256) : z4;
    uint4 Ahp = h1ok ? *(const uint4*)(A + v + 256) : z4;
    unsigned lfA = w0ok ? *(const unsigned*)(A + v - 1) : 0u;
    unsigned rtA = w1ok ? *(const unsigned*)(A + v + 4) : 0u;

    uint2 Bc  = *(const uint2*)(Bp + v);
    uint2 Bdm = d0ok ? *(const uint2*)(Bp + v - HW)  : z2;
    uint2 Bdp = d1ok ? *(const uint2*)(Bp + v + HW)  : z2;
    uint2 Bhm = h0ok ? *(const uint2*)(Bp + v - 256) : z2;
    uint2 Bhp = h1ok ? *(const uint2*)(Bp + v + 256) : z2;
    unsigned bL = w0ok ? *(const unsigned*)(Bp + v - 2) : 0u;
    unsigned bR = w1ok ? *(const unsigned*)(Bp + v + 4) : 0u;

    unsigned tc4 = *(const unsigned*)(Tb + v);
    unsigned tdm = d0ok ? *(const unsigned*)(Tb + v - HW)  : 0u;
    unsigned tdp = d1ok ? *(const unsigned*)(Tb + v + HW)  : 0u;
    unsigned thm = h0ok ? *(const unsigned*)(Tb + v - 256) : 0u;
    unsigned thp = h1ok ? *(const unsigned*)(Tb + v + 256) : 0u;
    unsigned twL = w0ok ? *(const unsigned*)(Tb + v - 4)   : 0u;
    unsigned twR = w1ok ? *(const unsigned*)(Tb + v + 4)   : 0u;

    // ---- A stencil: per voxel j, half2 = classes (1,2) ----
    const __half2 m6 = __floats2half2_rn(-6.f, -6.f);
    const __half2* cA = (const __half2*)&Ac;
    __half2 sA[4];
    {
        const __half2* dm = (const __half2*)&Adm;
        const __half2* dp = (const __half2*)&Adp;
        const __half2* hm = (const __half2*)&Ahm;
        const __half2* hp = (const __half2*)&Ahp;
#pragma unroll
        for (int j = 0; j < 4; ++j) {
            __half2 lf = (j == 0) ? u2h(lfA) : cA[j - 1];
            __half2 rt = (j == 3) ? u2h(rtA) : cA[j + 1];
            __half2 s = __hadd2(__hadd2(dm[j], dp[j]), __hadd2(hm[j], hp[j]));
            s = __hadd2(s, __hadd2(lf, rt));
            sA[j] = __hfma2(cA[j], m6, s);
        }
    }

    // ---- B stencil: pairs (v0,v1) and (v2,v3), class 3 ----
    unsigned L0  = __byte_perm(Bc.x, bL, 0x1076);   // (B[v-1], v0)
    unsigned mid = __byte_perm(Bc.x, Bc.y, 0x5432); // (v1, v2)
    unsigned R1  = __byte_perm(Bc.y, bR, 0x5432);   // (v3, B[v+4])
    __half2 sB0 = __hadd2(__hadd2(u2h(Bdm.x), u2h(Bdp.x)),
                          __hadd2(u2h(Bhm.x), u2h(Bhp.x)));
    sB0 = __hadd2(sB0, __hadd2(u2h(L0), u2h(mid)));
    sB0 = __hfma2(u2h(Bc.x), m6, sB0);
    __half2 sB1 = __hadd2(__hadd2(u2h(Bdm.y), u2h(Bdp.y)),
                          __hadd2(u2h(Bhm.y), u2h(Bhp.y)));
    sB1 = __hadd2(sB1, __hadd2(u2h(mid), u2h(R1)));
    sB1 = __hfma2(u2h(Bc.y), m6, sB1);

    // ---- byte-SIMD target |Laplacian| per class (values 0..6 per byte) ----
    unsigned lt4 = __byte_perm(tc4, twL, 0x2107);
    unsigned rt4 = __byte_perm(tc4, twR, 0x4321);
    const unsigned ONE = 0x01010101u;
    unsigned absT[3];
#pragma unroll
    for (int c = 0; c < 3; ++c) {
        unsigned cc = ONE * (unsigned)(c + 1);
        unsigned cnt = (__vcmpeq4(tdm, cc) & ONE) + (__vcmpeq4(tdp, cc) & ONE)
                     + (__vcmpeq4(thm, cc) & ONE) + (__vcmpeq4(thp, cc) & ONE)
                     + (__vcmpeq4(lt4, cc) & ONE) + (__vcmpeq4(rt4, cc) & ONE);
        unsigned e = __vcmpeq4(tc4, cc);           // 0xFF where center == class
        absT[c] = (cnt & ~e) | ((0x06060606u - cnt) & e);
    }

    // ---- loss accumulation ----
    float acc = 0.f;
#pragma unroll
    for (int j = 0; j < 4; ++j) {
        float2 f12 = __half22float2(__habs2(sA[j]));
        __half2 sb = (j < 2) ? sB0 : sB1;
        float f3 = fabsf((j & 1) ? __half2float(__high2half(sb))
                                 : __half2float(__low2half(sb)));
        float t1 = (float)((absT[0] >> (j * 8)) & 0xFFu);
        float t2 = (float)((absT[1] >> (j * 8)) & 0xFFu);
        float t3 = (float)((absT[2] >> (j * 8)) & 0xFFu);
        float d1 = f12.x - t1, d2 = f12.y - t2, d3 = f3 - t3;
        acc = fmaf(d1, d1, acc);
        acc = fmaf(d2, d2, acc);
        acc = fmaf(d3, d3, acc);
    }

    // ---- block reduction -> double atomic -> last-block finalize ----
#pragma unroll
    for (int o = 16; o; o >>= 1) acc += __shfl_down_sync(0xffffffffu, acc, o);
    __shared__ float ws[8];
    __shared__ unsigned ticket;
    int lane = threadIdx.x & 31, wid = threadIdx.x >> 5;
    if (lane == 0) ws[wid] = acc;
    __syncthreads();
    if (wid == 0) {
        acc = (lane < 8) ? ws[lane] : 0.f;
#pragma unroll
        for (int o = 4; o; o >>= 1) acc += __shfl_down_sync(0xffffffffu, acc, o);
        if (lane == 0) {
            atomicAdd(&g_acc, (double)acc);
            __threadfence();
            ticket = atomicAdd(&g_done, 1u);
        }
    }
    __syncthreads();
    if (threadIdx.x == 0 && ticket == gridDim.x - 1) {
        double total = atomicAdd(&g_acc, 0.0);
        out[0] = (float)(total * (1.0 / NELEM));
        g_done = 0;
    }
}

extern "C" void kernel_launch(void* const* d_in, const int* in_sizes, int n_in,
                              void* d_out, int out_size) {
    const float* logits  = (const float*)d_in[0];
    const int*   targets = (const int*)d_in[1];
    float* out = (float*)d_out;

    softmax_kernel<<<NQ / 256, 256>>>(logits, targets);
    loss_kernel<<<NQ / 256, 256>>>(out);
}

// round 16
// speedup vs baseline: 1.1936x; 1.0327x over previous
#include <cuda_runtime.h>
#include <cuda_fp16.h>

// Problem: B=2, C=4, D=64, H=256, W=256
#define HW     65536       // H*W (input layout)
#define DHW    4194304     // D*H*W
#define DHW4   1048576     // DHW/4
#define NQ     2097152     // threads, 4 voxels each
#define NELEM  25165824.0  // B*(C-1)*DHW

// Padded scratch layout: (D+2) x (H+2) x (W+8), halo stays zero forever
#define PROW   264                    // padded row stride (voxels)
#define PPLANE 68112                  // (H+2)*PROW = 258*264
#define PVOL   4495392                // (D+2)*PPLANE = 66*68112

// Planar scratch (zero-initialized at module load; halo never written):
// A = half2(p1,p2)/voxel, B = half(p3)/voxel, T = uint8 target/voxel
__device__ __align__(16) __half2       g_A[2 * PVOL];
__device__ __align__(16) __half        g_B[2 * PVOL];
__device__ __align__(16) unsigned char g_T[2 * PVOL];
__device__ double   g_acc;
__device__ unsigned g_done = 0;

__device__ __forceinline__ unsigned h2u(__half2 h) { return *(unsigned*)&h; }
__device__ __forceinline__ __half2 u2h(unsigned u) { return *(__half2*)&u; }

// ---------------- Pass 1: softmax + target byte-encode (padded stores) -------
__global__ void __launch_bounds__(256)
softmax_kernel(const float* __restrict__ logits, const int* __restrict__ targets) {
    int t = blockIdx.x * blockDim.x + threadIdx.x;
    if (t == 0) g_acc = 0.0;
    if (t >= NQ) return;
    int b  = t >> 20;
    int v4 = t & (DHW4 - 1);
    const float4* L = (const float4*)logits + (size_t)b * 4 * DHW4 + v4;
    float4 x0 = L[0 * DHW4];
    float4 x1 = L[1 * DHW4];
    float4 x2 = L[2 * DHW4];
    float4 x3 = L[3 * DHW4];
    float4 p1, p2, p3;
#define SM1(comp) {                                                       \
        float a = x0.comp, bb = x1.comp, c = x2.comp, dd = x3.comp;       \
        float m  = fmaxf(fmaxf(a, bb), fmaxf(c, dd));                     \
        float e0 = __expf(a - m), e1 = __expf(bb - m);                    \
        float e2 = __expf(c - m), e3 = __expf(dd - m);                    \
        float inv = __frcp_rn(e0 + e1 + e2 + e3);                        \
        p1.comp = e1 * inv; p2.comp = e2 * inv; p3.comp = e3 * inv; }
    SM1(x) SM1(y) SM1(z) SM1(w)
#undef SM1
    // padded interior address
    int d = v4 >> 14;
    int h = (v4 >> 6) & 255;
    int w = (v4 & 63) << 2;
    size_t pv = (size_t)b * PVOL + (size_t)(d + 1) * PPLANE
              + (size_t)(h + 1) * PROW + (w + 4);
    uint4 a4;
    a4.x = h2u(__floats2half2_rn(p1.x, p2.x));
    a4.y = h2u(__floats2half2_rn(p1.y, p2.y));
    a4.z = h2u(__floats2half2_rn(p1.z, p2.z));
    a4.w = h2u(__floats2half2_rn(p1.w, p2.w));
    *(uint4*)(g_A + pv) = a4;
    uint2 b2;
    b2.x = h2u(__floats2half2_rn(p3.x, p3.y));
    b2.y = h2u(__floats2half2_rn(p3.z, p3.w));
    *(uint2*)(g_B + pv) = b2;
    int4 tt = *((const int4*)targets + ((size_t)b * DHW4) + v4);
    unsigned tw = (unsigned)tt.x | ((unsigned)tt.y << 8)
                | ((unsigned)tt.z << 16) | ((unsigned)tt.w << 24);
    *(unsigned*)(g_T + pv) = tw;
}

// ---------------- Pass 2: stencil + loss, NO boundary predication ------------
__global__ void __launch_bounds__(256, 5)
loss_kernel(float* __restrict__ out) {
    int t  = blockIdx.x * blockDim.x + threadIdx.x;
    int w4 = t & 63;
    int h  = (t >> 6) & 255;
    int d  = (t >> 14) & 63;
    int b  = t >> 20;
    size_t v = (size_t)b * PVOL + (size_t)(d + 1) * PPLANE
             + (size_t)(h + 1) * PROW + ((w4 << 2) + 4);

    const __half2*       A  = g_A;
    const __half*        Bp = g_B;
    const unsigned char* Tb = g_T;

    // ---- loads (all unconditional; halo is zero) ----
    uint4 Ac  = *(const uint4*)(A + v);
    uint4 Adm = *(const uint4*)(A + v - PPLANE);
    uint4 Adp = *(const uint4*)(A + v + PPLANE);
    uint4 Ahm = *(const uint4*)(A + v - PROW);
    uint4 Ahp = *(const uint4*)(A + v + PROW);
    unsigned lfA = *(const unsigned*)(A + v - 1);
    unsigned rtA = *(const unsigned*)(A + v + 4);

    uint2 Bc  = *(const uint2*)(Bp + v);
    uint2 Bdm = *(const uint2*)(Bp + v - PPLANE);
    uint2 Bdp = *(const uint2*)(Bp + v + PPLANE);
    uint2 Bhm = *(const uint2*)(Bp + v - PROW);
    uint2 Bhp = *(const uint2*)(Bp + v + PROW);
    unsigned bL = *(const unsigned*)(Bp + v - 2);
    unsigned bR = *(const unsigned*)(Bp + v + 4);

    unsigned tc4 = *(const unsigned*)(Tb + v);
    unsigned tdm = *(const unsigned*)(Tb + v - PPLANE);
    unsigned tdp = *(const unsigned*)(Tb + v + PPLANE);
    unsigned thm = *(const unsigned*)(Tb + v - PROW);
    unsigned thp = *(const unsigned*)(Tb + v + PROW);
    unsigned twL = *(const unsigned*)(Tb + v - 4);
    unsigned twR = *(const unsigned*)(Tb + v + 4);

    // ---- A stencil: per voxel j, half2 = classes (1,2) ----
    const __half2 m6 = __floats2half2_rn(-6.f, -6.f);
    const __half2* cA = (const __half2*)&Ac;
    __half2 sA[4];
    {
        const __half2* dm = (const __half2*)&Adm;
        const __half2* dp = (const __half2*)&Adp;
        const __half2* hm = (const __half2*)&Ahm;
        const __half2* hp = (const __half2*)&Ahp;
#pragma unroll
        for (int j = 0; j < 4; ++j) {
            __half2 lf = (j == 0) ? u2h(lfA) : cA[j - 1];
            __half2 rt = (j == 3) ? u2h(rtA) : cA[j + 1];
            __half2 s = __hadd2(__hadd2(dm[j], dp[j]), __hadd2(hm[j], hp[j]));
            s = __hadd2(s, __hadd2(lf, rt));
            sA[j] = __hfma2(cA[j], m6, s);
        }
    }

    // ---- B stencil: pairs (v0,v1) and (v2,v3), class 3 ----
    unsigned L0  = __byte_perm(Bc.x, bL, 0x1076);   // (B[v-1], v0)
    unsigned mid = __byte_perm(Bc.x, Bc.y, 0x5432); // (v1, v2)
    unsigned R1  = __byte_perm(Bc.y, bR, 0x5432);   // (v3, B[v+4])
    __half2 sB0 = __hadd2(__hadd2(u2h(Bdm.x), u2h(Bdp.x)),
                          __hadd2(u2h(Bhm.x), u2h(Bhp.x)));
    sB0 = __hadd2(sB0, __hadd2(u2h(L0), u2h(mid)));
    sB0 = __hfma2(u2h(Bc.x), m6, sB0);
    __half2 sB1 = __hadd2(__hadd2(u2h(Bdm.y), u2h(Bdp.y)),
                          __hadd2(u2h(Bhm.y), u2h(Bhp.y)));
    sB1 = __hadd2(sB1, __hadd2(u2h(mid), u2h(R1)));
    sB1 = __hfma2(u2h(Bc.y), m6, sB1);

    // ---- byte-SIMD target |Laplacian| per class (values 0..6 per byte) ----
    unsigned lt4 = __byte_perm(tc4, twL, 0x2107);
    unsigned rt4 = __byte_perm(tc4, twR, 0x4321);
    const unsigned ONE = 0x01010101u;
    unsigned absT[3];
#pragma unroll
    for (int c = 0; c < 3; ++c) {
        unsigned cc = ONE * (unsigned)(c + 1);
        unsigned cnt = (__vcmpeq4(tdm, cc) & ONE) + (__vcmpeq4(tdp, cc) & ONE)
                     + (__vcmpeq4(thm, cc) & ONE) + (__vcmpeq4(thp, cc) & ONE)
                     + (__vcmpeq4(lt4, cc) & ONE) + (__vcmpeq4(rt4, cc) & ONE);
        unsigned e = __vcmpeq4(tc4, cc);           // 0xFF where center == class
        absT[c] = (cnt & ~e) | ((0x06060606u - cnt) & e);
    }

    // ---- loss accumulation ----
    float acc = 0.f;
#pragma unroll
    for (int j = 0; j < 4; ++j) {
        float2 f12 = __half22float2(__habs2(sA[j]));
        __half2 sb = (j < 2) ? sB0 : sB1;
        float f3 = fabsf((j & 1) ? __half2float(__high2half(sb))
                                 : __half2float(__low2half(sb)));
        float t1 = (float)((absT[0] >> (j * 8)) & 0xFFu);
        float t2 = (float)((absT[1] >> (j * 8)) & 0xFFu);
        float t3 = (float)((absT[2] >> (j * 8)) & 0xFFu);
        float d1 = f12.x - t1, d2 = f12.y - t2, d3 = f3 - t3;
        acc = fmaf(d1, d1, acc);
        acc = fmaf(d2, d2, acc);
        acc = fmaf(d3, d3, acc);
    }

    // ---- block reduction -> double atomic -> last-block finalize ----
#pragma unroll
    for (int o = 16; o; o >>= 1) acc += __shfl_down_sync(0xffffffffu, acc, o);
    __shared__ float ws[8];
    __shared__ unsigned ticket;
    int lane = threadIdx.x & 31, wid = threadIdx.x >> 5;
    if (lane == 0) ws[wid] = acc;
    __syncthreads();
    if (wid == 0) {
        acc = (lane < 8) ? ws[lane] : 0.f;
#pragma unroll
        for (int o = 4; o; o >>= 1) acc += __shfl_down_sync(0xffffffffu, acc, o);
        if (lane == 0) {
            atomicAdd(&g_acc, (double)acc);
            __threadfence();
            ticket = atomicAdd(&g_done, 1u);
        }
    }
    __syncthreads();
    if (threadIdx.x == 0 && ticket == gridDim.x - 1) {
        double total = atomicAdd(&g_acc, 0.0);
        out[0] = (float)(total * (1.0 / NELEM));
        g_done = 0;
    }
}

extern "C" void kernel_launch(void* const* d_in, const int* in_sizes, int n_in,
                              void* d_out, int out_size) {
    const float* logits  = (const float*)d_in[0];
    const int*   targets = (const int*)d_in[1];
    float* out = (float*)d_out;

    softmax_kernel<<<NQ / 256, 256>>>(logits, targets);
    loss_kernel<<<NQ / 256, 256>>>(out);
}

// round 17
// speedup vs baseline: 1.2340x; 1.0338x over previous
#include <cuda_runtime.h>
#include <cuda_fp16.h>

// Problem: B=2, C=4, D=64, H=256, W=256
#define HW     65536       // H*W (input layout)
#define DHW    4194304     // D*H*W
#define DHW4   1048576     // DHW/4
#define NQ     2097152     // threads, 4 voxels each
#define NELEM  25165824.0  // B*(C-1)*DHW

// Padded scratch layout: (D+2) x (H+2) x (W+8), halo stays zero forever
#define PROW   264                    // padded row stride (voxels)
#define PPLANE 68112                  // (H+2)*PROW = 258*264
#define PVOL   4495392                // (D+2)*PPLANE = 66*68112

// Planar scratch (zero-initialized at module load; halo never written):
// A = half2(p1,p2)/voxel, B = half(p3)/voxel, T = uint8 target/voxel
__device__ __align__(16) __half2       g_A[2 * PVOL];
__device__ __align__(16) __half        g_B[2 * PVOL];
__device__ __align__(16) unsigned char g_T[2 * PVOL];
__device__ double   g_acc;
__device__ unsigned g_done = 0;

__device__ __forceinline__ unsigned h2u(__half2 h) { return *(unsigned*)&h; }
__device__ __forceinline__ __half2 u2h(unsigned u) { return *(__half2*)&u; }

// ---------------- Pass 1: softmax + target byte-encode (padded stores) -------
__global__ void __launch_bounds__(256)
softmax_kernel(const float* __restrict__ logits, const int* __restrict__ targets) {
    int t = blockIdx.x * blockDim.x + threadIdx.x;
    if (t == 0) g_acc = 0.0;
    if (t >= NQ) return;
    int b  = t >> 20;
    int v4 = t & (DHW4 - 1);
    const float4* L = (const float4*)logits + (size_t)b * 4 * DHW4 + v4;
    float4 x0 = L[0 * DHW4];
    float4 x1 = L[1 * DHW4];
    float4 x2 = L[2 * DHW4];
    float4 x3 = L[3 * DHW4];
    float4 p1, p2, p3;
#define SM1(comp) {                                                       \
        float a = x0.comp, bb = x1.comp, c = x2.comp, dd = x3.comp;       \
        float m  = fmaxf(fmaxf(a, bb), fmaxf(c, dd));                     \
        float e0 = __expf(a - m), e1 = __expf(bb - m);                    \
        float e2 = __expf(c - m), e3 = __expf(dd - m);                    \
        float inv = __frcp_rn(e0 + e1 + e2 + e3);                        \
        p1.comp = e1 * inv; p2.comp = e2 * inv; p3.comp = e3 * inv; }
    SM1(x) SM1(y) SM1(z) SM1(w)
#undef SM1
    int d = v4 >> 14;
    int h = (v4 >> 6) & 255;
    int w = (v4 & 63) << 2;
    size_t pv = (size_t)b * PVOL + (size_t)(d + 1) * PPLANE
              + (size_t)(h + 1) * PROW + (w + 4);
    uint4 a4;
    a4.x = h2u(__floats2half2_rn(p1.x, p2.x));
    a4.y = h2u(__floats2half2_rn(p1.y, p2.y));
    a4.z = h2u(__floats2half2_rn(p1.z, p2.z));
    a4.w = h2u(__floats2half2_rn(p1.w, p2.w));
    *(uint4*)(g_A + pv) = a4;
    uint2 b2;
    b2.x = h2u(__floats2half2_rn(p3.x, p3.y));
    b2.y = h2u(__floats2half2_rn(p3.z, p3.w));
    *(uint2*)(g_B + pv) = b2;
    int4 tt = *((const int4*)targets + ((size_t)b * DHW4) + v4);
    unsigned tw = (unsigned)tt.x | ((unsigned)tt.y << 8)
                | ((unsigned)tt.z << 16) | ((unsigned)tt.w << 24);
    *(unsigned*)(g_T + pv) = tw;
}

// ---------------- Pass 2: phased loads, occ 6, no predication ----------------
__global__ void __launch_bounds__(256, 6)
loss_kernel(float* __restrict__ out) {
    int t  = blockIdx.x * blockDim.x + threadIdx.x;
    int w4 = t & 63;
    int h  = (t >> 6) & 255;
    int d  = (t >> 14) & 63;
    int b  = t >> 20;
    size_t v = (size_t)b * PVOL + (size_t)(d + 1) * PPLANE
             + (size_t)(h + 1) * PROW + ((w4 << 2) + 4);

    const __half2 m6 = __floats2half2_rn(-6.f, -6.f);

    // ======== Phase A: classes (1,2) ========
    __half2 sA[4];
    {
        const __half2* A = g_A;
        uint4 Ac  = *(const uint4*)(A + v);
        uint4 Adm = *(const uint4*)(A + v - PPLANE);
        uint4 Adp = *(const uint4*)(A + v + PPLANE);
        uint4 Ahm = *(const uint4*)(A + v - PROW);
        uint4 Ahp = *(const uint4*)(A + v + PROW);
        unsigned lfA = *(const unsigned*)(A + v - 1);
        unsigned rtA = *(const unsigned*)(A + v + 4);
        const __half2* cA = (const __half2*)&Ac;
        const __half2* dm = (const __half2*)&Adm;
        const __half2* dp = (const __half2*)&Adp;
        const __half2* hm = (const __half2*)&Ahm;
        const __half2* hp = (const __half2*)&Ahp;
#pragma unroll
        for (int j = 0; j < 4; ++j) {
            __half2 lf = (j == 0) ? u2h(lfA) : cA[j - 1];
            __half2 rt = (j == 3) ? u2h(rtA) : cA[j + 1];
            __half2 s = __hadd2(__hadd2(dm[j], dp[j]), __hadd2(hm[j], hp[j]));
            s = __hadd2(s, __hadd2(lf, rt));
            sA[j] = __hfma2(cA[j], m6, s);
        }
    }

    // ======== Phase B: class 3 ========
    __half2 sB0, sB1;
    {
        const __half* Bp = g_B;
        uint2 Bc  = *(const uint2*)(Bp + v);
        uint2 Bdm = *(const uint2*)(Bp + v - PPLANE);
        uint2 Bdp = *(const uint2*)(Bp + v + PPLANE);
        uint2 Bhm = *(const uint2*)(Bp + v - PROW);
        uint2 Bhp = *(const uint2*)(Bp + v + PROW);
        unsigned bL = *(const unsigned*)(Bp + v - 2);
        unsigned bR = *(const unsigned*)(Bp + v + 4);
        unsigned L0  = __byte_perm(Bc.x, bL, 0x1076);   // (B[v-1], v0)
        unsigned mid = __byte_perm(Bc.x, Bc.y, 0x5432); // (v1, v2)
        unsigned R1  = __byte_perm(Bc.y, bR, 0x5432);   // (v3, B[v+4])
        sB0 = __hadd2(__hadd2(u2h(Bdm.x), u2h(Bdp.x)),
                      __hadd2(u2h(Bhm.x), u2h(Bhp.x)));
        sB0 = __hadd2(sB0, __hadd2(u2h(L0), u2h(mid)));
        sB0 = __hfma2(u2h(Bc.x), m6, sB0);
        sB1 = __hadd2(__hadd2(u2h(Bdm.y), u2h(Bdp.y)),
                      __hadd2(u2h(Bhm.y), u2h(Bhp.y)));
        sB1 = __hadd2(sB1, __hadd2(u2h(mid), u2h(R1)));
        sB1 = __hfma2(u2h(Bc.y), m6, sB1);
    }

    // ======== Phase T: byte-SIMD target |Laplacian| per class ========
    unsigned absT[3];
    {
        const unsigned char* Tb = g_T;
        unsigned tc4 = *(const unsigned*)(Tb + v);
        unsigned tdm = *(const unsigned*)(Tb + v - PPLANE);
        unsigned tdp = *(const unsigned*)(Tb + v + PPLANE);
        unsigned thm = *(const unsigned*)(Tb + v - PROW);
        unsigned thp = *(const unsigned*)(Tb + v + PROW);
        unsigned twL = *(const unsigned*)(Tb + v - 4);
        unsigned twR = *(const unsigned*)(Tb + v + 4);
        unsigned lt4 = __byte_perm(tc4, twL, 0x2107);
        unsigned rt4 = __byte_perm(tc4, twR, 0x4321);
        const unsigned ONE = 0x01010101u;
#pragma unroll
        for (int c = 0; c < 3; ++c) {
            unsigned cc = ONE * (unsigned)(c + 1);
            unsigned cnt = (__vcmpeq4(tdm, cc) & ONE) + (__vcmpeq4(tdp, cc) & ONE)
                         + (__vcmpeq4(thm, cc) & ONE) + (__vcmpeq4(thp, cc) & ONE)
                         + (__vcmpeq4(lt4, cc) & ONE) + (__vcmpeq4(rt4, cc) & ONE);
            unsigned e = __vcmpeq4(tc4, cc);       // 0xFF where center == class
            absT[c] = (cnt & ~e) | ((0x06060606u - cnt) & e);
        }
    }

    // ======== accumulate ========
    float acc = 0.f;
#pragma unroll
    for (int j = 0; j < 4; ++j) {
        float2 f12 = __half22float2(__habs2(sA[j]));
        __half2 sb = (j < 2) ? sB0 : sB1;
        float f3 = fabsf((j & 1) ? __half2float(__high2half(sb))
                                 : __half2float(__low2half(sb)));
        float t1 = (float)((absT[0] >> (j * 8)) & 0xFFu);
        float t2 = (float)((absT[1] >> (j * 8)) & 0xFFu);
        float t3 = (float)((absT[2] >> (j * 8)) & 0xFFu);
        float d1 = f12.x - t1, d2 = f12.y - t2, d3 = f3 - t3;
        acc = fmaf(d1, d1, acc);
        acc = fmaf(d2, d2, acc);
        acc = fmaf(d3, d3, acc);
    }

    // ---- block reduction -> double atomic -> last-block finalize ----
#pragma unroll
    for (int o = 16; o; o >>= 1) acc += __shfl_down_sync(0xffffffffu, acc, o);
    __shared__ float ws[8];
    __shared__ unsigned ticket;
    int lane = threadIdx.x & 31, wid = threadIdx.x >> 5;
    if (lane == 0) ws[wid] = acc;
    __syncthreads();
    if (wid == 0) {
        acc = (lane < 8) ? ws[lane] : 0.f;
#pragma unroll
        for (int o = 4; o; o >>= 1) acc += __shfl_down_sync(0xffffffffu, acc, o);
        if (lane == 0) {
            atomicAdd(&g_acc, (double)acc);
            __threadfence();
            ticket = atomicAdd(&g_done, 1u);
        }
    }
    __syncthreads();
    if (threadIdx.x == 0 && ticket == gridDim.x - 1) {
        double total = atomicAdd(&g_acc, 0.0);
        out[0] = (float)(total * (1.0 / NELEM));
        g_done = 0;
    }
}

extern "C" void kernel_launch(void* const* d_in, const int* in_sizes, int n_in,
                              void* d_out, int out_size) {
    const float* logits  = (const float*)d_in[0];
    const int*   targets = (const int*)d_in[1];
    float* out = (float*)d_out;

    softmax_kernel<<<NQ / 256, 256>>>(logits, targets);
    loss_kernel<<<NQ / 256, 256>>>(out);
}